// round 2
// baseline (speedup 1.0000x reference)
#include <cuda_runtime.h>
#include <cstdint>

#define NTOK  524288      // 16*32*32*32
#define BATCH 32
#define ROWS  64          // 2 sides * 32 batch
#define NB1   8192        // pass-1 buckets: float bits >> 19
#define CAPC  131072      // candidate list capacity per row

static __device__ __forceinline__ float clampf(float x) {
    return fminf(fmaxf(x, 1e-3f), 0.999f);
}

// ---------------- scratch (static device allocations only) ----------------
__device__ float              d_tab[2][BATCH][112];   // Ev[16] Et[32] Eh[32] Ew[32]
__device__ int                d_Kc[2];
__device__ unsigned int       d_hist[ROWS][NB1];      // 2 MB
__device__ int                d_b1[ROWS];
__device__ int                d_R[ROWS];
__device__ unsigned long long d_cand[ROWS][CAPC];     // 64 MB: (key<<32)|idx
__device__ int                d_cc[ROWS];

// ---------------- k_setup: pow tables + K ----------------
__global__ void k_setup(const float* __restrict__ comps, const int* __restrict__ idxp,
                        const float* __restrict__ ur_s, const float* __restrict__ ur_t,
                        const float* __restrict__ uv_s, const float* __restrict__ ut_s,
                        const float* __restrict__ uh_s, const float* __restrict__ uw_s,
                        const float* __restrict__ uv_t, const float* __restrict__ ut_t,
                        const float* __restrict__ uh_t, const float* __restrict__ uw_t)
{
    int id = idxp[0];
    float ia0 = 1.0f / comps[id*4+0];
    float ia1 = 1.0f / comps[id*4+1];
    float ia2 = 1.0f / comps[id*4+2];
    float ia3 = 1.0f / comps[id*4+3];
    for (int e = threadIdx.x; e < 2*BATCH*112; e += blockDim.x) {
        int side = e / (BATCH*112);
        int rem  = e % (BATCH*112);
        int b = rem / 112;
        int j = rem % 112;
        const float* uv = side ? uv_t : uv_s;
        const float* ut = side ? ut_t : ut_s;
        const float* uh = side ? uh_t : uh_s;
        const float* uw = side ? uw_t : uw_s;
        float val, ia;
        if (j < 16)      { val = uv[b*16 +  j     ]; ia = ia0; }
        else if (j < 48) { val = ut[b*32 + (j-16)]; ia = ia1; }
        else if (j < 80) { val = uh[b*32 + (j-48)]; ia = ia2; }
        else             { val = uw[b*32 + (j-80)]; ia = ia3; }
        d_tab[side][b][j] = powf(clampf(val), ia);
    }
    if (threadIdx.x == 0) d_Kc[0] = (int)(clampf(ur_s[0]) * (float)NTOK);
    if (threadIdx.x == 1) d_Kc[1] = (int)(clampf(ur_t[0]) * (float)NTOK);
}

// ---------------- k_zero: reset hist + counters (graph replays!) ----------------
__global__ void k_zero() {
    int i = blockIdx.x * blockDim.x + threadIdx.x;
    if (i < ROWS * NB1) ((unsigned int*)d_hist)[i] = 0u;
    if (i < ROWS) d_cc[i] = 0;
}

// ---------------- pass 1: histogram of key top-13 bits ----------------
__global__ void __launch_bounds__(1024) k_hist(const float* __restrict__ u0s,
                                               const float* __restrict__ u0t)
{
    __shared__ unsigned int sh[NB1];
    __shared__ float stab[112];
    int row   = blockIdx.x >> 2;
    int chunk = blockIdx.x & 3;
    int side  = row >> 5, b = row & 31;
    int t = threadIdx.x;
    for (int i = t; i < NB1; i += 1024) sh[i] = 0u;
    if (t < 112) stab[t] = d_tab[side][b][t];
    __syncthreads();

    const float4* src = (const float4*)((side ? u0t : u0s) + (size_t)b * NTOK);
    int base4 = chunk * 32768;
    #pragma unroll 4
    for (int it = 0; it < 32; it++) {
        int idx4 = base4 + it * 1024 + t;
        float4 u = src[idx4];
        int n  = idx4 << 2;
        int v  =  n >> 15;
        int tt = (n >> 10) & 31;
        int h  = (n >> 5)  & 31;
        int w0 =  n & 31;
        float pre = stab[v] * stab[16+tt] * stab[48+h];
        float k0 = clampf(u.x) * pre * stab[80+w0];
        float k1 = clampf(u.y) * pre * stab[80+w0+1];
        float k2 = clampf(u.z) * pre * stab[80+w0+2];
        float k3 = clampf(u.w) * pre * stab[80+w0+3];
        atomicAdd(&sh[__float_as_uint(k0) >> 19], 1u);
        atomicAdd(&sh[__float_as_uint(k1) >> 19], 1u);
        atomicAdd(&sh[__float_as_uint(k2) >> 19], 1u);
        atomicAdd(&sh[__float_as_uint(k3) >> 19], 1u);
    }
    __syncthreads();
    for (int i = t; i < NB1; i += 1024)
        if (sh[i]) atomicAdd(&d_hist[row][i], sh[i]);
}

// ---------------- k_scan: find threshold bucket per row ----------------
__global__ void __launch_bounds__(256) k_scan()
{
    __shared__ unsigned int sh[NB1];
    __shared__ unsigned int spart[256];
    __shared__ unsigned int sexcl[256];
    int row = blockIdx.x;
    int t = threadIdx.x;
    for (int i = t; i < NB1; i += 256) sh[i] = d_hist[row][i];
    __syncthreads();
    unsigned int s = 0;
    for (int j = 0; j < 32; j++) s += sh[8191 - (t*32 + j)];   // descending buckets
    spart[t] = s;
    __syncthreads();
    if (t == 0) {
        unsigned int c = 0;
        for (int i = 0; i < 256; i++) { sexcl[i] = c; c += spart[i]; }
    }
    __syncthreads();
    unsigned int K = (unsigned int)d_Kc[row >> 5];
    unsigned int ex = sexcl[t];
    if (ex < K && K <= ex + spart[t]) {
        unsigned int cum = ex;
        for (int j = 0; j < 32; j++) {
            unsigned int hh = sh[8191 - (t*32 + j)];
            if (cum + hh >= K) { d_b1[row] = 8191 - (t*32 + j); d_R[row] = (int)(K - cum); break; }
            cum += hh;
        }
    }
}

// ---------------- pass 2: provisional float mask + candidate gather ----------------
__global__ void __launch_bounds__(1024) k_mask(const float* __restrict__ u0s,
                                               const float* __restrict__ u0t,
                                               float* __restrict__ out)
{
    __shared__ float stab[112];
    int row   = blockIdx.x >> 2;
    int chunk = blockIdx.x & 3;
    int side  = row >> 5, b = row & 31;
    int t = threadIdx.x;
    if (t < 112) stab[t] = d_tab[side][b][t];
    __syncthreads();
    unsigned int b1 = (unsigned int)d_b1[row];

    const float4* src = (const float4*)((side ? u0t : u0s) + (size_t)b * NTOK);
    float4* out4 = (float4*)(out + (size_t)row * NTOK);
    int lane = t & 31;
    unsigned int lmask = (1u << lane) - 1u;

    int base4 = chunk * 32768;
    for (int it = 0; it < 32; it++) {
        int idx4 = base4 + it * 1024 + t;
        float4 u = src[idx4];
        int n  = idx4 << 2;
        int v  =  n >> 15;
        int tt = (n >> 10) & 31;
        int h  = (n >> 5)  & 31;
        int w0 =  n & 31;
        float pre = stab[v] * stab[16+tt] * stab[48+h];
        unsigned int kb[4];
        kb[0] = __float_as_uint(clampf(u.x) * pre * stab[80+w0]);
        kb[1] = __float_as_uint(clampf(u.y) * pre * stab[80+w0+1]);
        kb[2] = __float_as_uint(clampf(u.z) * pre * stab[80+w0+2]);
        kb[3] = __float_as_uint(clampf(u.w) * pre * stab[80+w0+3]);
        float m[4];
        #pragma unroll
        for (int j = 0; j < 4; j++) {
            unsigned int bk = kb[j] >> 19;
            m[j] = (bk > b1) ? 1.0f : 0.0f;
            bool cand = (bk == b1);
            unsigned int mball = __ballot_sync(0xffffffffu, cand);
            if (mball) {
                int leader = __ffs(mball) - 1;
                int basepos = 0;
                if (lane == leader) basepos = atomicAdd(&d_cc[row], __popc(mball));
                basepos = __shfl_sync(0xffffffffu, basepos, leader);
                if (cand) {
                    int pos = basepos + __popc(mball & lmask);
                    if (pos < CAPC)
                        d_cand[row][pos] = ((unsigned long long)kb[j] << 32) | (unsigned int)(n + j);
                }
            }
        }
        out4[idx4] = make_float4(m[0], m[1], m[2], m[3]);
    }
}

// ---------------- block reduce helper ----------------
static __device__ __forceinline__ unsigned int blk_reduce_1024(unsigned int v, unsigned int* s33)
{
    unsigned int wv = __reduce_add_sync(0xffffffffu, v);
    int lane = threadIdx.x & 31, w = threadIdx.x >> 5;
    __syncthreads();
    if (lane == 0) s33[w] = wv;
    __syncthreads();
    if (threadIdx.x < 32) {
        unsigned int x = s33[threadIdx.x];
        x = __reduce_add_sync(0xffffffffu, x);
        if (threadIdx.x == 0) s33[32] = x;
    }
    __syncthreads();
    return s33[32];
}

// ---------------- k_select: exact threshold + tie-break, fix candidate bits ----------------
__global__ void __launch_bounds__(1024) k_select(float* __restrict__ out)
{
    __shared__ unsigned int s33[33];
    int row = blockIdx.x;
    int t = threadIdx.x;
    int c = min(d_cc[row], CAPC);
    unsigned int R  = (unsigned int)d_R[row];
    unsigned int b1 = (unsigned int)d_b1[row];
    const unsigned long long* cand = d_cand[row];

    // binary search exact threshold key within bucket b1 (19 unknown low bits)
    unsigned int lo = b1 << 19;
    unsigned int hi = lo + ((1u << 19) - 1u);
    while (lo < hi) {
        unsigned int mid = lo + ((hi - lo + 1u) >> 1);
        unsigned int local = 0;
        for (int i = t; i < c; i += 1024)
            local += ((unsigned int)(cand[i] >> 32) >= mid);
        unsigned int cnt = blk_reduce_1024(local, s33);
        if (cnt >= R) lo = mid; else hi = mid - 1u;
    }
    unsigned int Tkey = lo;

    // strictly-greater count -> how many equals to take (stable by index)
    unsigned int local = 0;
    for (int i = t; i < c; i += 1024)
        local += ((unsigned int)(cand[i] >> 32) > Tkey);
    unsigned int cntGT = blk_reduce_1024(local, s33);
    unsigned int R3 = R - cntGT;   // >= 1

    // smallest index I* s.t. count(key==Tkey && idx<=I*) >= R3
    unsigned int ilo = 0, ihi = NTOK - 1;
    while (ilo < ihi) {
        unsigned int mid = (ilo + ihi) >> 1;
        unsigned int l2 = 0;
        for (int i = t; i < c; i += 1024) {
            unsigned long long cd = cand[i];
            l2 += (((unsigned int)(cd >> 32) == Tkey) && ((unsigned int)cd <= mid));
        }
        unsigned int cnt = blk_reduce_1024(l2, s33);
        if (cnt >= R3) ihi = mid; else ilo = mid + 1u;
    }
    unsigned int Istar = ilo;

    // write selected candidates
    float* orow = out + (size_t)row * NTOK;
    for (int i = t; i < c; i += 1024) {
        unsigned long long cd = cand[i];
        unsigned int kb = (unsigned int)(cd >> 32);
        unsigned int n  = (unsigned int)cd;
        if (kb > Tkey || (kb == Tkey && n <= Istar)) orow[n] = 1.0f;
    }
}

// ---------------- launch ----------------
extern "C" void kernel_launch(void* const* d_in, const int* in_sizes, int n_in,
                              void* d_out, int out_size)
{
    const float* comps = (const float*)d_in[0];
    const float* ur_s  = (const float*)d_in[1];
    const float* ur_t  = (const float*)d_in[2];
    const float* u0s   = (const float*)d_in[3];
    const float* u0t   = (const float*)d_in[4];
    const float* uv_s  = (const float*)d_in[5];
    const float* ut_s  = (const float*)d_in[6];
    const float* uh_s  = (const float*)d_in[7];
    const float* uw_s  = (const float*)d_in[8];
    const float* uv_t  = (const float*)d_in[9];
    const float* ut_t  = (const float*)d_in[10];
    const float* uh_t  = (const float*)d_in[11];
    const float* uw_t  = (const float*)d_in[12];
    const int*   idx   = (const int*)d_in[13];
    float* out = (float*)d_out;

    k_setup<<<1, 256>>>(comps, idx, ur_s, ur_t,
                        uv_s, ut_s, uh_s, uw_s,
                        uv_t, ut_t, uh_t, uw_t);
    k_zero<<<512, 1024>>>();
    k_hist<<<256, 1024>>>(u0s, u0t);
    k_scan<<<64, 256>>>();
    k_mask<<<256, 1024>>>(u0s, u0t, out);
    k_select<<<64, 1024>>>(out);
}